// round 16
// baseline (speedup 1.0000x reference)
#include <cuda_runtime.h>
#include <cstdint>

#define N_TOK  32768
#define KDIM   2048
#define NEXP   64
#define TOPK   6
#define TM     64              // tokens per CTA (GEMM)
#define KC     32              // K per staged chunk
#define NCHUNK (KDIM / KC)     // 64
#define LDPAD  36              // padded row (floats); 144B rows, 16B-aligned

// scratch for scores (allocation-free rule: __device__ global)
__device__ float g_scores[(size_t)N_TOK * NEXP];

// TF32 round-to-nearest-away (cuBLAS/cutlass conversion)
__device__ __forceinline__ float tf32r(float x) {
    uint32_t r;
    asm("cvt.rna.tf32.f32 %0, %1;" : "=r"(r) : "f"(x));
    return __uint_as_float(r);
}

#define MMA_TF32(acc, A0, A1, A2, A3, B0, B1)                                  \
    asm volatile(                                                              \
        "mma.sync.aligned.m16n8k8.row.col.f32.tf32.tf32.f32 "                  \
        "{%0,%1,%2,%3}, {%4,%5,%6,%7}, {%8,%9}, {%0,%1,%2,%3};"                \
        : "+f"(acc[0]), "+f"(acc[1]), "+f"(acc[2]), "+f"(acc[3])               \
        : "r"(A0), "r"(A1), "r"(A2), "r"(A3), "r"(B0), "r"(B1))

// ============================================================
// Kernel 1: scores = x @ w^T via 3xTF32 mma.sync (m16n8k8).
// (validated round-15 kernel, unchanged; ~162us measured)
// ============================================================
__global__ __launch_bounds__(128)
void gemm_3xtf32_kernel(const float* __restrict__ x, const float* __restrict__ w) {
    __shared__ float Ah[TM * LDPAD];
    __shared__ float Al[TM * LDPAD];
    __shared__ float Bh[NEXP * LDPAD];
    __shared__ float Bl[NEXP * LDPAD];

    const int tid  = threadIdx.x;
    const int lane = tid & 31;
    const int wid  = tid >> 5;
    const int t0   = blockIdx.x * TM;
    const int r4   = lane >> 2;
    const int c4   = lane & 3;

    float acc[8][4] = {};

    float4 ra[4], rb[4];
#pragma unroll
    for (int i = 0; i < 4; i++) {
        int gi = tid + 128 * i, row = gi >> 3, cc = gi & 7;
        ra[i] = *(const float4*)(x + (size_t)(t0 + row) * KDIM + cc * 4);
        rb[i] = *(const float4*)(w + (size_t)row * KDIM + cc * 4);
    }

    for (int c = 0; c < NCHUNK; c++) {
        __syncthreads();
#pragma unroll
        for (int i = 0; i < 4; i++) {
            int gi = tid + 128 * i, row = gi >> 3, cc = gi & 7;
            float4 v = ra[i];
            float4 h, l;
            h.x = tf32r(v.x); l.x = tf32r(v.x - h.x);
            h.y = tf32r(v.y); l.y = tf32r(v.y - h.y);
            h.z = tf32r(v.z); l.z = tf32r(v.z - h.z);
            h.w = tf32r(v.w); l.w = tf32r(v.w - h.w);
            *(float4*)&Ah[row * LDPAD + cc * 4] = h;
            *(float4*)&Al[row * LDPAD + cc * 4] = l;
            v = rb[i];
            h.x = tf32r(v.x); l.x = tf32r(v.x - h.x);
            h.y = tf32r(v.y); l.y = tf32r(v.y - h.y);
            h.z = tf32r(v.z); l.z = tf32r(v.z - h.z);
            h.w = tf32r(v.w); l.w = tf32r(v.w - h.w);
            *(float4*)&Bh[row * LDPAD + cc * 4] = h;
            *(float4*)&Bl[row * LDPAD + cc * 4] = l;
        }
        __syncthreads();

        if (c + 1 < NCHUNK) {
            const int k0 = (c + 1) * KC;
#pragma unroll
            for (int i = 0; i < 4; i++) {
                int gi = tid + 128 * i, row = gi >> 3, cc = gi & 7;
                ra[i] = *(const float4*)(x + (size_t)(t0 + row) * KDIM + k0 + cc * 4);
                rb[i] = *(const float4*)(w + (size_t)row * KDIM + k0 + cc * 4);
            }
        }

#pragma unroll
        for (int ks = 0; ks < 4; ks++) {
            const int kk = ks * 8;
            const int arow = wid * 16 + r4;
            uint32_t ah0 = __float_as_uint(Ah[(arow)     * LDPAD + kk + c4]);
            uint32_t ah1 = __float_as_uint(Ah[(arow + 8) * LDPAD + kk + c4]);
            uint32_t ah2 = __float_as_uint(Ah[(arow)     * LDPAD + kk + c4 + 4]);
            uint32_t ah3 = __float_as_uint(Ah[(arow + 8) * LDPAD + kk + c4 + 4]);
            uint32_t al0 = __float_as_uint(Al[(arow)     * LDPAD + kk + c4]);
            uint32_t al1 = __float_as_uint(Al[(arow + 8) * LDPAD + kk + c4]);
            uint32_t al2 = __float_as_uint(Al[(arow)     * LDPAD + kk + c4 + 4]);
            uint32_t al3 = __float_as_uint(Al[(arow + 8) * LDPAD + kk + c4 + 4]);
#pragma unroll
            for (int nb = 0; nb < 8; nb++) {
                const int brow = nb * 8 + r4;
                uint32_t bh0 = __float_as_uint(Bh[brow * LDPAD + kk + c4]);
                uint32_t bh1 = __float_as_uint(Bh[brow * LDPAD + kk + c4 + 4]);
                uint32_t bl0 = __float_as_uint(Bl[brow * LDPAD + kk + c4]);
                uint32_t bl1 = __float_as_uint(Bl[brow * LDPAD + kk + c4 + 4]);
                MMA_TF32(acc[nb], ah0, ah1, ah2, ah3, bh0, bh1);  // hi*hi
                MMA_TF32(acc[nb], ah0, ah1, ah2, ah3, bl0, bl1);  // hi*lo
                MMA_TF32(acc[nb], al0, al1, al2, al3, bh0, bh1);  // lo*hi
            }
        }
    }

    const int row0 = t0 + wid * 16 + r4;
#pragma unroll
    for (int nb = 0; nb < 8; nb++) {
        *(float2*)(g_scores + (size_t)row0 * NEXP + nb * 8 + 2 * c4) =
            make_float2(acc[nb][0], acc[nb][1]);
        *(float2*)(g_scores + (size_t)(row0 + 8) * NEXP + nb * 8 + 2 * c4) =
            make_float2(acc[nb][2], acc[nb][3]);
    }
}

// FTZ emulation of XLA-GPU softmax tail (validated):
#define FLT_MIN_N 1.17549435082228751e-38f
// near-cutoff band: +-0.5% around FLT_MIN (d-band ~1e-2 >> max tensor noise ~2e-4)
__device__ __forceinline__ bool near_ftz(float v) {
    return v > 0.995f * FLT_MIN_N && v < 1.005f * FLT_MIN_N;
}
#define GAP_REL 1e-3f   // relative p-gap ambiguity (d-gap ~1e-3 >> noise 2e-4)

// ============================================================
// Kernel 2: softmax + top-6, straight-line hot path (validated
// round-10 shape), ambiguity flags, cold exact-recompute tail.
// out: [N_TOK*TOPK] weights fp32, then [N_TOK*TOPK] indices as fp32
// ============================================================
__global__ __launch_bounds__(256)
void softmax_topk_fix_kernel(const float* __restrict__ x, const float* __restrict__ w,
                             float* __restrict__ out, int write_idx) {
    const int warp = threadIdx.x >> 5;
    const int lane = threadIdx.x & 31;
    const int t = blockIdx.x * 8 + warp;
    if (t >= N_TOK) return;

    const float* s = g_scores + (size_t)t * NEXP;
    float v0 = s[lane];
    float v1 = s[lane + 32];

    // ---------------- hot path ----------------
    float m = fmaxf(v0, v1);
#pragma unroll
    for (int o = 16; o; o >>= 1) m = fmaxf(m, __shfl_xor_sync(0xffffffffu, m, o));

    float er0 = expf(v0 - m);
    float er1 = expf(v1 - m);
    bool nf = near_ftz(er0) || near_ftz(er1);          // pre-flush band check
    float e0 = (er0 < FLT_MIN_N) ? 0.0f : er0;
    float e1 = (er1 < FLT_MIN_N) ? 0.0f : er1;
    float sum = e0 + e1;
#pragma unroll
    for (int o = 16; o; o >>= 1) sum += __shfl_xor_sync(0xffffffffu, sum, o);

    float p0r = __fdiv_rn(e0, sum);
    float p1r = __fdiv_rn(e1, sum);
    nf = nf || near_ftz(p0r) || near_ftz(p1r);
    float p0 = (p0r < FLT_MIN_N) ? 0.0f : p0r;
    float p1 = (p1r < FLT_MIN_N) ? 0.0f : p1r;

    // 7 selection rounds (6 outputs + 1 for the in/out-of-top-6 gap)
    float wv[6]; int we[6];
    float pv0 = p0, pv1 = p1;
    bool gapflag = false;
    float prev = 0.0f;
#pragma unroll
    for (int r = 0; r < 7; r++) {
        float bv; int bi;
        if (pv0 >= pv1) { bv = pv0; bi = lane; }
        else            { bv = pv1; bi = lane + 32; }
#pragma unroll
        for (int o = 16; o; o >>= 1) {
            float ov = __shfl_xor_sync(0xffffffffu, bv, o);
            int   oi = __shfl_xor_sync(0xffffffffu, bi, o);
            if (ov > bv || (ov == bv && oi < bi)) { bv = ov; bi = oi; }
        }
        // relative p-gap test (zero plateau excluded: ties there are exact)
        if (r > 0 && bv > 0.0f && bv >= prev * (1.0f - GAP_REL)) gapflag = true;
        prev = bv;
        if (r < 6) { wv[r] = bv; we[r] = bi; }
        if (bi == lane)      pv0 = -1.0f;
        if (bi == lane + 32) pv1 = -1.0f;
    }

    if (!__any_sync(0xffffffffu, nf) && !gapflag) {
        if (lane == 0) {
#pragma unroll
            for (int r = 0; r < TOPK; r++) {
                out[(size_t)t * TOPK + r] = wv[r];           // ROUTE_SCALE = 1
                if (write_idx)
                    out[(size_t)N_TOK * TOPK + (size_t)t * TOPK + r] = (float)we[r];
            }
        }
        return;
    }

    // ---------------- cold path (~0.3% of tokens) ----------------
    // exact recompute: ascending-k fmaf chain (bitwise = validated fp32 chain)
    {
        const float4* xr = (const float4*)(x + (size_t)t * KDIM);
        const float4* w0 = (const float4*)(w + (size_t)lane * KDIM);
        const float4* w1 = (const float4*)(w + (size_t)(lane + 32) * KDIM);
        float a0 = 0.0f, a1 = 0.0f;
#pragma unroll 4
        for (int k4 = 0; k4 < KDIM / 4; k4++) {
            float4 xv = xr[k4];
            float4 u  = w0[k4];
            float4 q  = w1[k4];
            a0 = fmaf(xv.x, u.x, a0); a1 = fmaf(xv.x, q.x, a1);
            a0 = fmaf(xv.y, u.y, a0); a1 = fmaf(xv.y, q.y, a1);
            a0 = fmaf(xv.z, u.z, a0); a1 = fmaf(xv.z, q.z, a1);
            a0 = fmaf(xv.w, u.w, a0); a1 = fmaf(xv.w, q.w, a1);
        }
        v0 = a0;
        v1 = a1;
    }

    float m2 = fmaxf(v0, v1);
#pragma unroll
    for (int o = 16; o; o >>= 1) m2 = fmaxf(m2, __shfl_xor_sync(0xffffffffu, m2, o));

    float f0 = expf(v0 - m2);
    float f1 = expf(v1 - m2);
    if (f0 < FLT_MIN_N) f0 = 0.0f;
    if (f1 < FLT_MIN_N) f1 = 0.0f;
    float sum2 = f0 + f1;
#pragma unroll
    for (int o = 16; o; o >>= 1) sum2 += __shfl_xor_sync(0xffffffffu, sum2, o);

    float q0 = __fdiv_rn(f0, sum2);
    float q1 = __fdiv_rn(f1, sum2);
    if (q0 < FLT_MIN_N) q0 = 0.0f;
    if (q1 < FLT_MIN_N) q1 = 0.0f;

#pragma unroll
    for (int r = 0; r < TOPK; r++) {
        float bv; int bi;
        if (q0 >= q1) { bv = q0; bi = lane; }
        else          { bv = q1; bi = lane + 32; }
#pragma unroll
        for (int o = 16; o; o >>= 1) {
            float ov = __shfl_xor_sync(0xffffffffu, bv, o);
            int   oi = __shfl_xor_sync(0xffffffffu, bi, o);
            if (ov > bv || (ov == bv && oi < bi)) { bv = ov; bi = oi; }
        }
        if (lane == 0) {
            out[(size_t)t * TOPK + r] = bv;
            if (write_idx)
                out[(size_t)N_TOK * TOPK + (size_t)t * TOPK + r] = (float)bi;
        }
        if (bi == lane)      q0 = -1.0f;
        if (bi == lane + 32) q1 = -1.0f;
    }
}

extern "C" void kernel_launch(void* const* d_in, const int* in_sizes, int n_in,
                              void* d_out, int out_size) {
    const float* x = (const float*)d_in[0];   // [32768, 2048] fp32
    const float* w = (const float*)d_in[1];   // [64, 2048] fp32
    float* out = (float*)d_out;

    gemm_3xtf32_kernel<<<N_TOK / TM, 128>>>(x, w);

    const int write_idx = (out_size >= 2 * N_TOK * TOPK) ? 1 : 0;
    softmax_topk_fix_kernel<<<N_TOK / 8, 256>>>(x, w, out, write_idx);
}